// round 4
// baseline (speedup 1.0000x reference)
#include <cuda_runtime.h>
#include <cuda_fp16.h>

#define NMAX   100000
#define VOCAB  32
#define NTYPE  16
#define EMB    64
#define MSGD   128
#define EEMB   32
#define CIN    (EMB + EEMB)      // 96
#define NPAIR  (VOCAB * NTYPE)   // 512
#define G3     192               // 3*EMB
#define CAP    96                // per-node bucket capacity (multiple of 8)

// ---------------- static scratch ----------------
// Padded gather table: 513 rows (512 pairs + 1 zero null-row), each row = 32 lanes x 16B.
// Lane L's uint4 holds halves {M2[L], M2[L+32], M2[L+64], M2[L+96], M2[L+128], M2[L+160], pad, pad}
__device__ __align__(16) uint4 g_tab[(NPAIR + 1) * 32];      // ~257 KB
__device__ float g_gh[VOCAB * G3];                            //  24 KB
__device__ int   g_deg[NMAX];                                 // zeroed via memsetAsync
__device__ __align__(16) unsigned short g_pairs2[NMAX * CAP]; // 19.2 MB buckets

// ---------------- fused front-end: tables + bucket scatter ----------------
// blocks [0,512): per-(vocab,type) msg->M2 table rows
// block 512: zero the null row
// blocks [513, 513+32): gh table
// rest: scatter, 768 edges per block (192 thr x 4)
__global__ void __launch_bounds__(192) k_work(
    const int* __restrict__ nid, const int* __restrict__ src,
    const int* __restrict__ dst, const int* __restrict__ typ, int E,
    const float* __restrict__ emb, const float* __restrict__ eemb,
    const float* __restrict__ W1, const float* __restrict__ b1,
    const float* __restrict__ W2, const float* __restrict__ b2,
    const float* __restrict__ W_ih,
    const float* __restrict__ W_hh, const float* __restrict__ b_hh) {
    int b = blockIdx.x, tid = threadIdx.x;
    if (b < NPAIR) {
        __shared__ float x[CIN];
        __shared__ float hid[MSGD];
        __shared__ float msg[MSGD];
        __shared__ float m2[G3];
        int v = b >> 4, t = b & 15;
        if (tid < EMB)       x[tid] = emb[v * EMB + tid];
        else if (tid < CIN)  x[tid] = eemb[t * EEMB + (tid - EMB)];
        __syncthreads();
        if (tid < MSGD) {
            float s = b1[tid];
            #pragma unroll 8
            for (int i = 0; i < CIN; i++) s += x[i] * W1[i * MSGD + tid];
            hid[tid] = fmaxf(s, 0.f);
        }
        __syncthreads();
        if (tid < MSGD) {
            float m = b2[tid];
            #pragma unroll 8
            for (int i = 0; i < MSGD; i++) m += hid[i] * W2[i * MSGD + tid];
            msg[tid] = m;
        }
        __syncthreads();
        {
            float s = 0.f;
            #pragma unroll 8
            for (int j = 0; j < MSGD; j++) s += msg[j] * W_ih[j * G3 + tid];
            m2[tid] = s;
        }
        __syncthreads();
        if (tid < 128) {
            int L = tid >> 2, s = tid & 3;          // lane, half2 slot
            __half2 val = (s < 3)
                ? __floats2half2_rn(m2[L + 64 * s], m2[L + 64 * s + 32])
                : __float2half2_rn(0.f);
            reinterpret_cast<__half2*>(g_tab)[b * 128 + L * 4 + s] = val;
        }
    } else if (b == NPAIR) {
        if (tid < 128)
            reinterpret_cast<__half2*>(g_tab)[NPAIR * 128 + tid] = __float2half2_rn(0.f);
    } else if (b < NPAIR + 1 + VOCAB) {
        __shared__ float h[EMB];
        int v = b - NPAIR - 1;
        if (tid < EMB) h[tid] = emb[v * EMB + tid];
        __syncthreads();
        float s = b_hh[tid];
        #pragma unroll 8
        for (int j = 0; j < EMB; j++) s += h[j] * W_hh[j * G3 + tid];
        g_gh[v * G3 + tid] = s;
    } else {
        int base = (b - NPAIR - 1 - VOCAB) * 768 + tid * 4;
        if (base + 3 < E) {
            int4 s4 = *(const int4*)(src + base);
            int4 d4 = *(const int4*)(dst + base);
            int4 t4 = *(const int4*)(typ + base);
            #pragma unroll
            for (int k = 0; k < 4; k++) {
                int d = (&d4.x)[k];
                unsigned short p = (unsigned short)((nid[(&s4.x)[k]] << 4) | (&t4.x)[k]);
                int pos = atomicAdd(&g_deg[d], 1);
                if (pos < CAP) g_pairs2[d * CAP + pos] = p;
            }
        } else {
            for (int e = base; e < E; e++) {
                int d = dst[e];
                unsigned short p = (unsigned short)((nid[src[e]] << 4) | typ[e]);
                int pos = atomicAdd(&g_deg[d], 1);
                if (pos < CAP) g_pairs2[d * CAP + pos] = p;
            }
        }
    }
}

// ---------------- fused gather + GRU + score: one warp per node ----------------
__device__ __forceinline__ float sigmoidf_(float x) { return 1.f / (1.f + __expf(-x)); }

__global__ void __launch_bounds__(256) k_main(
    const int* __restrict__ nid, const float* __restrict__ emb,
    const float* __restrict__ b_ih, const float* __restrict__ score_w,
    const float* __restrict__ score_b, float* __restrict__ out, int N) {
    int d = (blockIdx.x * blockDim.x + threadIdx.x) >> 5;
    int lane = threadIdx.x & 31;
    if (d >= N) return;

    int deg = g_deg[d];
    int degc = min(deg, CAP);
    const unsigned short* pl = &g_pairs2[d * CAP];

    float a0 = 0.f, a1 = 0.f, a2 = 0.f, a3 = 0.f, a4 = 0.f, a5 = 0.f;

    int c = 0;
    // full 8-edge chunks: no bounds checks
    for (; c + 8 <= degc; c += 8) {
        uint4 pk = *(const uint4*)(pl + c);                   // 8 pair ids, broadcast
        __half2 h0 = __float2half2_rn(0.f);
        __half2 h1 = h0, h2 = h0;
        unsigned w[4] = {pk.x, pk.y, pk.z, pk.w};
        #pragma unroll
        for (int q = 0; q < 4; q++) {
            unsigned p0 = w[q] & 0xFFFFu;
            unsigned p1 = w[q] >> 16;
            uint4 v0 = __ldg(&g_tab[p0 * 32 + lane]);
            h0 = __hadd2(h0, *reinterpret_cast<__half2*>(&v0.x));
            h1 = __hadd2(h1, *reinterpret_cast<__half2*>(&v0.y));
            h2 = __hadd2(h2, *reinterpret_cast<__half2*>(&v0.z));
            uint4 v1 = __ldg(&g_tab[p1 * 32 + lane]);
            h0 = __hadd2(h0, *reinterpret_cast<__half2*>(&v1.x));
            h1 = __hadd2(h1, *reinterpret_cast<__half2*>(&v1.y));
            h2 = __hadd2(h2, *reinterpret_cast<__half2*>(&v1.z));
        }
        float2 f0 = __half22float2(h0);
        float2 f1 = __half22float2(h1);
        float2 f2 = __half22float2(h2);
        a0 += f0.x; a1 += f0.y; a2 += f1.x; a3 += f1.y; a4 += f2.x; a5 += f2.y;
    }
    // tail chunk: redirect out-of-range slots to the zero null-row
    if (c < degc) {
        uint4 pk = *(const uint4*)(pl + c);                   // safe: c <= 88, row = 96
        __half2 h0 = __float2half2_rn(0.f);
        __half2 h1 = h0, h2 = h0;
        unsigned w[4] = {pk.x, pk.y, pk.z, pk.w};
        int m = degc - c;
        #pragma unroll
        for (int q = 0; q < 4; q++) {
            unsigned p0 = (2 * q     < m) ? (w[q] & 0xFFFFu) : (unsigned)NPAIR;
            unsigned p1 = (2 * q + 1 < m) ? (w[q] >> 16)     : (unsigned)NPAIR;
            uint4 v0 = __ldg(&g_tab[p0 * 32 + lane]);
            h0 = __hadd2(h0, *reinterpret_cast<__half2*>(&v0.x));
            h1 = __hadd2(h1, *reinterpret_cast<__half2*>(&v0.y));
            h2 = __hadd2(h2, *reinterpret_cast<__half2*>(&v0.z));
            uint4 v1 = __ldg(&g_tab[p1 * 32 + lane]);
            h0 = __hadd2(h0, *reinterpret_cast<__half2*>(&v1.x));
            h1 = __hadd2(h1, *reinterpret_cast<__half2*>(&v1.y));
            h2 = __hadd2(h2, *reinterpret_cast<__half2*>(&v1.z));
        }
        float2 f0 = __half22float2(h0);
        float2 f1 = __half22float2(h1);
        float2 f2 = __half22float2(h2);
        a0 += f0.x; a1 += f0.y; a2 += f1.x; a3 += f1.y; a4 += f2.x; a5 += f2.y;
    }

    float inv = 1.f / fmaxf((float)deg, 1.f);
    int v = nid[d];
    const float* gh = &g_gh[v * G3];

    float r0 = sigmoidf_(a0 * inv + b_ih[lane]        + gh[lane]);
    float r1 = sigmoidf_(a1 * inv + b_ih[lane + 32]   + gh[lane + 32]);
    float z0 = sigmoidf_(a2 * inv + b_ih[lane + 64]   + gh[lane + 64]);
    float z1 = sigmoidf_(a3 * inv + b_ih[lane + 96]   + gh[lane + 96]);
    float n0 = tanhf(a4 * inv + b_ih[lane + 128] + r0 * gh[lane + 128]);
    float n1 = tanhf(a5 * inv + b_ih[lane + 160] + r1 * gh[lane + 160]);

    float h0 = emb[v * EMB + lane];
    float h1 = emb[v * EMB + lane + 32];
    float hn0 = (1.f - z0) * n0 + z0 * h0;
    float hn1 = (1.f - z1) * n1 + z1 * h1;

    float part = hn0 * score_w[lane] + hn1 * score_w[lane + 32];
    #pragma unroll
    for (int o = 16; o > 0; o >>= 1) part += __shfl_down_sync(0xffffffffu, part, o);
    if (lane == 0) out[d] = part + score_b[0];
}

// ---------------- launcher ----------------
extern "C" void kernel_launch(void* const* d_in, const int* in_sizes, int n_in,
                              void* d_out, int out_size) {
    const int*   node_ids  = (const int*)  d_in[0];
    const int*   edge_src  = (const int*)  d_in[1];
    const int*   edge_dst  = (const int*)  d_in[2];
    const int*   edge_type = (const int*)  d_in[3];
    const float* emb       = (const float*)d_in[4];
    const float* eemb      = (const float*)d_in[5];
    const float* W1        = (const float*)d_in[6];
    const float* b1        = (const float*)d_in[7];
    const float* W2        = (const float*)d_in[8];
    const float* b2        = (const float*)d_in[9];
    const float* W_ih      = (const float*)d_in[10];
    const float* W_hh      = (const float*)d_in[11];
    const float* b_ih      = (const float*)d_in[12];
    const float* b_hh      = (const float*)d_in[13];
    const float* score_w   = (const float*)d_in[14];
    const float* score_b   = (const float*)d_in[15];
    float* out = (float*)d_out;

    int N = in_sizes[0];
    int E = in_sizes[1];

    void* degp = nullptr;
    cudaGetSymbolAddress(&degp, g_deg);
    cudaMemsetAsync(degp, 0, (size_t)N * sizeof(int));

    int scat_blocks = (E + 767) / 768;
    k_work<<<NPAIR + 1 + VOCAB + scat_blocks, 192>>>(
        node_ids, edge_src, edge_dst, edge_type, E,
        emb, eemb, W1, b1, W2, b2, W_ih, W_hh, b_hh);

    k_main<<<(N * 32 + 255) / 256, 256>>>(node_ids, emb, b_ih, score_w, score_b, out, N);
}

// round 5
// speedup vs baseline: 1.0752x; 1.0752x over previous
#include <cuda_runtime.h>
#include <cuda_fp16.h>

#define NMAX   100000
#define VOCAB  32
#define NTYPE  16
#define EMB    64
#define MSGD   128
#define EEMB   32
#define CIN    (EMB + EEMB)      // 96
#define NPAIR  (VOCAB * NTYPE)   // 512
#define G3     192               // 3*EMB
#define H2C    96                // half2 per table row: (M2[i], M2[i+96])
#define CAP    96                // per-node bucket capacity (multiple of 8)
#define NSM    148
#define MAIN_THREADS 1024
#define TAB_H2 ((NPAIR + 1) * H2C)            // incl. zero null-row
#define TAB_BYTES (TAB_H2 * 4)                // 196,992 B

// ---------------- static scratch ----------------
__device__ __align__(16) __half2 g_M2h[TAB_H2];               // 192.4 KB master table
__device__ float g_gh[VOCAB * G3];                            //  24 KB: emb @ W_hh + b_hh
__device__ int   g_deg[NMAX];                                 // zeroed via memsetAsync
__device__ __align__(16) unsigned short g_pairs2[NMAX * CAP]; // 19.2 MB buckets

// ---------------- fused front-end: tables + bucket scatter ----------------
__global__ void __launch_bounds__(192) k_work(
    const int* __restrict__ nid, const int* __restrict__ src,
    const int* __restrict__ dst, const int* __restrict__ typ, int E,
    const float* __restrict__ emb, const float* __restrict__ eemb,
    const float* __restrict__ W1, const float* __restrict__ b1,
    const float* __restrict__ W2, const float* __restrict__ b2,
    const float* __restrict__ W_ih,
    const float* __restrict__ W_hh, const float* __restrict__ b_hh) {
    int b = blockIdx.x, tid = threadIdx.x;
    if (b < NPAIR) {
        __shared__ float x[CIN];
        __shared__ float hid[MSGD];
        __shared__ float msg[MSGD];
        __shared__ float m2[G3];
        int v = b >> 4, t = b & 15;
        if (tid < EMB)       x[tid] = emb[v * EMB + tid];
        else if (tid < CIN)  x[tid] = eemb[t * EEMB + (tid - EMB)];
        __syncthreads();
        if (tid < MSGD) {
            float s = b1[tid];
            #pragma unroll 8
            for (int i = 0; i < CIN; i++) s += x[i] * W1[i * MSGD + tid];
            hid[tid] = fmaxf(s, 0.f);
        }
        __syncthreads();
        if (tid < MSGD) {
            float m = b2[tid];
            #pragma unroll 8
            for (int i = 0; i < MSGD; i++) m += hid[i] * W2[i * MSGD + tid];
            msg[tid] = m;
        }
        __syncthreads();
        {
            float s = 0.f;
            #pragma unroll 8
            for (int j = 0; j < MSGD; j++) s += msg[j] * W_ih[j * G3 + tid];
            m2[tid] = s;
        }
        __syncthreads();
        if (tid < H2C)
            g_M2h[b * H2C + tid] = __floats2half2_rn(m2[tid], m2[tid + H2C]);
    } else if (b == NPAIR) {
        if (tid < H2C) g_M2h[NPAIR * H2C + tid] = __float2half2_rn(0.f);  // null row
    } else if (b < NPAIR + 1 + VOCAB) {
        __shared__ float h[EMB];
        int v = b - NPAIR - 1;
        if (tid < EMB) h[tid] = emb[v * EMB + tid];
        __syncthreads();
        float s = b_hh[tid];
        #pragma unroll 8
        for (int j = 0; j < EMB; j++) s += h[j] * W_hh[j * G3 + tid];
        g_gh[v * G3 + tid] = s;
    } else {
        int base = (b - NPAIR - 1 - VOCAB) * 768 + tid * 4;
        if (base + 3 < E) {
            int4 s4 = *(const int4*)(src + base);
            int4 d4 = *(const int4*)(dst + base);
            int4 t4 = *(const int4*)(typ + base);
            #pragma unroll
            for (int k = 0; k < 4; k++) {
                int d = (&d4.x)[k];
                unsigned short p = (unsigned short)((nid[(&s4.x)[k]] << 4) | (&t4.x)[k]);
                int pos = atomicAdd(&g_deg[d], 1);
                if (pos < CAP) g_pairs2[d * CAP + pos] = p;
            }
        } else {
            for (int e = base; e < E; e++) {
                int d = dst[e];
                unsigned short p = (unsigned short)((nid[src[e]] << 4) | typ[e]);
                int pos = atomicAdd(&g_deg[d], 1);
                if (pos < CAP) g_pairs2[d * CAP + pos] = p;
            }
        }
    }
}

// ---------------- persistent gather + GRU + score, table in smem ----------------
__device__ __forceinline__ float sigmoidf_(float x) { return 1.f / (1.f + __expf(-x)); }

__global__ void __launch_bounds__(MAIN_THREADS, 1) k_main(
    const int* __restrict__ nid, const float* __restrict__ emb,
    const float* __restrict__ b_ih, const float* __restrict__ score_w,
    const float* __restrict__ score_b, float* __restrict__ out, int N) {
    extern __shared__ __align__(16) __half2 stab[];   // (NPAIR+1) x 96 half2

    // cooperative table load: 192.4 KB as uint4 (12312 vectors)
    {
        const uint4* gsrc = reinterpret_cast<const uint4*>(g_M2h);
        uint4* sdst = reinterpret_cast<uint4*>(stab);
        int nv = TAB_H2 / 4;                          // 12312
        for (int i = threadIdx.x; i < nv; i += MAIN_THREADS) sdst[i] = gsrc[i];
    }
    __syncthreads();

    int wid  = threadIdx.x >> 5;
    int lane = threadIdx.x & 31;
    int gwarp = blockIdx.x * (MAIN_THREADS / 32) + wid;
    const int WTOT = NSM * (MAIN_THREADS / 32);       // 4736

    for (int d = gwarp; d < N; d += WTOT) {
        int deg = g_deg[d];
        int degc = min(deg, CAP);
        const unsigned short* pl = &g_pairs2[d * CAP];

        float a0 = 0.f, a1 = 0.f, a2 = 0.f, a3 = 0.f, a4 = 0.f, a5 = 0.f;
        for (int c = 0; c < degc; c += 8) {
            uint4 pk = *(const uint4*)(pl + c);       // 8 pair ids (broadcast)
            __half2 h0 = __float2half2_rn(0.f), h1 = h0, h2 = h0;
            unsigned w[4] = {pk.x, pk.y, pk.z, pk.w};
            int m = degc - c;
            if (m >= 8) {
                #pragma unroll
                for (int q = 0; q < 4; q++) {
                    unsigned p0 = w[q] & 0xFFFFu;
                    unsigned p1 = w[q] >> 16;
                    const __half2* r0 = &stab[p0 * H2C + lane];
                    const __half2* r1 = &stab[p1 * H2C + lane];
                    h0 = __hadd2(h0, r0[0]);
                    h1 = __hadd2(h1, r0[32]);
                    h2 = __hadd2(h2, r0[64]);
                    h0 = __hadd2(h0, r1[0]);
                    h1 = __hadd2(h1, r1[32]);
                    h2 = __hadd2(h2, r1[64]);
                }
            } else {
                #pragma unroll
                for (int q = 0; q < 4; q++) {
                    unsigned p0 = (2 * q     < m) ? (w[q] & 0xFFFFu) : (unsigned)NPAIR;
                    unsigned p1 = (2 * q + 1 < m) ? (w[q] >> 16)     : (unsigned)NPAIR;
                    const __half2* r0 = &stab[p0 * H2C + lane];
                    const __half2* r1 = &stab[p1 * H2C + lane];
                    h0 = __hadd2(h0, r0[0]);
                    h1 = __hadd2(h1, r0[32]);
                    h2 = __hadd2(h2, r0[64]);
                    h0 = __hadd2(h0, r1[0]);
                    h1 = __hadd2(h1, r1[32]);
                    h2 = __hadd2(h2, r1[64]);
                }
            }
            float2 f0 = __half22float2(h0);
            float2 f1 = __half22float2(h1);
            float2 f2 = __half22float2(h2);
            a0 += f0.x; a3 += f0.y;
            a1 += f1.x; a4 += f1.y;
            a2 += f2.x; a5 += f2.y;
        }

        float inv = 1.f / fmaxf((float)deg, 1.f);
        int v = nid[d];
        const float* gh = &g_gh[v * G3];

        float r0 = sigmoidf_(a0 * inv + __ldg(&b_ih[lane])       + gh[lane]);
        float r1 = sigmoidf_(a1 * inv + __ldg(&b_ih[lane + 32])  + gh[lane + 32]);
        float z0 = sigmoidf_(a2 * inv + __ldg(&b_ih[lane + 64])  + gh[lane + 64]);
        float z1 = sigmoidf_(a3 * inv + __ldg(&b_ih[lane + 96])  + gh[lane + 96]);
        float n0 = tanhf(a4 * inv + __ldg(&b_ih[lane + 128]) + r0 * gh[lane + 128]);
        float n1 = tanhf(a5 * inv + __ldg(&b_ih[lane + 160]) + r1 * gh[lane + 160]);

        float h0 = __ldg(&emb[v * EMB + lane]);
        float h1 = __ldg(&emb[v * EMB + lane + 32]);
        float hn0 = (1.f - z0) * n0 + z0 * h0;
        float hn1 = (1.f - z1) * n1 + z1 * h1;

        float part = hn0 * __ldg(&score_w[lane]) + hn1 * __ldg(&score_w[lane + 32]);
        #pragma unroll
        for (int o = 16; o > 0; o >>= 1) part += __shfl_down_sync(0xffffffffu, part, o);
        if (lane == 0) out[d] = part + score_b[0];
    }
}

// ---------------- launcher ----------------
extern "C" void kernel_launch(void* const* d_in, const int* in_sizes, int n_in,
                              void* d_out, int out_size) {
    const int*   node_ids  = (const int*)  d_in[0];
    const int*   edge_src  = (const int*)  d_in[1];
    const int*   edge_dst  = (const int*)  d_in[2];
    const int*   edge_type = (const int*)  d_in[3];
    const float* emb       = (const float*)d_in[4];
    const float* eemb      = (const float*)d_in[5];
    const float* W1        = (const float*)d_in[6];
    const float* b1        = (const float*)d_in[7];
    const float* W2        = (const float*)d_in[8];
    const float* b2        = (const float*)d_in[9];
    const float* W_ih      = (const float*)d_in[10];
    const float* W_hh      = (const float*)d_in[11];
    const float* b_ih      = (const float*)d_in[12];
    const float* b_hh      = (const float*)d_in[13];
    const float* score_w   = (const float*)d_in[14];
    const float* score_b   = (const float*)d_in[15];
    float* out = (float*)d_out;

    int N = in_sizes[0];
    int E = in_sizes[1];

    // allow the large dynamic smem (idempotent; no allocation involved)
    cudaFuncSetAttribute(k_main, cudaFuncAttributeMaxDynamicSharedMemorySize, TAB_BYTES);

    void* degp = nullptr;
    cudaGetSymbolAddress(&degp, g_deg);
    cudaMemsetAsync(degp, 0, (size_t)N * sizeof(int));

    int scat_blocks = (E + 767) / 768;
    k_work<<<NPAIR + 1 + VOCAB + scat_blocks, 192>>>(
        node_ids, edge_src, edge_dst, edge_type, E,
        emb, eemb, W1, b1, W2, b2, W_ih, W_hh, b_hh);

    k_main<<<NSM, MAIN_THREADS, TAB_BYTES>>>(node_ids, emb, b_ih, score_w, score_b, out, N);
}

// round 6
// speedup vs baseline: 1.0765x; 1.0012x over previous
#include <cuda_runtime.h>
#include <cuda_fp16.h>

#define NMAX   100000
#define VOCAB  32
#define NTYPE  16
#define EMB    64
#define MSGD   128
#define EEMB   32
#define CIN    (EMB + EEMB)      // 96
#define NPAIR  (VOCAB * NTYPE)   // 512
#define G3     192               // 3*EMB
#define H2C    96                // half2 per table row: (M2[i], M2[i+96])
#define CAP    96                // per-node bucket capacity (multiple of 8)

// ---------------- static scratch ----------------
__device__ __align__(16) __half2 g_M2h[(NPAIR + 1) * H2C];    // 192.4 KB (+ zero null-row), L1-resident
__device__ float g_gh[VOCAB * G3];                            //  24 KB: emb @ W_hh + b_hh
__device__ int   g_deg[NMAX];                                 // zeroed via memsetAsync
__device__ __align__(16) unsigned short g_pairs2[NMAX * CAP]; // 19.2 MB buckets

// ---------------- fused front-end: tables + bucket scatter ----------------
__global__ void __launch_bounds__(192) k_work(
    const int* __restrict__ nid, const int* __restrict__ src,
    const int* __restrict__ dst, const int* __restrict__ typ, int E,
    const float* __restrict__ emb, const float* __restrict__ eemb,
    const float* __restrict__ W1, const float* __restrict__ b1,
    const float* __restrict__ W2, const float* __restrict__ b2,
    const float* __restrict__ W_ih,
    const float* __restrict__ W_hh, const float* __restrict__ b_hh) {
    int b = blockIdx.x, tid = threadIdx.x;
    if (b < NPAIR) {
        __shared__ float x[CIN];
        __shared__ float hid[MSGD];
        __shared__ float msg[MSGD];
        __shared__ float m2[G3];
        int v = b >> 4, t = b & 15;
        if (tid < EMB)       x[tid] = emb[v * EMB + tid];
        else if (tid < CIN)  x[tid] = eemb[t * EEMB + (tid - EMB)];
        __syncthreads();
        if (tid < MSGD) {
            float s = b1[tid];
            #pragma unroll 8
            for (int i = 0; i < CIN; i++) s += x[i] * W1[i * MSGD + tid];
            hid[tid] = fmaxf(s, 0.f);
        }
        __syncthreads();
        if (tid < MSGD) {
            float m = b2[tid];
            #pragma unroll 8
            for (int i = 0; i < MSGD; i++) m += hid[i] * W2[i * MSGD + tid];
            msg[tid] = m;
        }
        __syncthreads();
        {
            float s = 0.f;
            #pragma unroll 8
            for (int j = 0; j < MSGD; j++) s += msg[j] * W_ih[j * G3 + tid];
            m2[tid] = s;
        }
        __syncthreads();
        if (tid < H2C)
            g_M2h[b * H2C + tid] = __floats2half2_rn(m2[tid], m2[tid + H2C]);
    } else if (b == NPAIR) {
        if (tid < H2C) g_M2h[NPAIR * H2C + tid] = __float2half2_rn(0.f);  // null row
    } else if (b < NPAIR + 1 + VOCAB) {
        __shared__ float h[EMB];
        int v = b - NPAIR - 1;
        if (tid < EMB) h[tid] = emb[v * EMB + tid];
        __syncthreads();
        float s = b_hh[tid];
        #pragma unroll 8
        for (int j = 0; j < EMB; j++) s += h[j] * W_hh[j * G3 + tid];
        g_gh[v * G3 + tid] = s;
    } else {
        int base = (b - NPAIR - 1 - VOCAB) * 768 + tid * 4;
        if (base + 3 < E) {
            int4 s4 = *(const int4*)(src + base);
            int4 d4 = *(const int4*)(dst + base);
            int4 t4 = *(const int4*)(typ + base);
            #pragma unroll
            for (int k = 0; k < 4; k++) {
                int d = (&d4.x)[k];
                unsigned short p = (unsigned short)((nid[(&s4.x)[k]] << 4) | (&t4.x)[k]);
                int pos = atomicAdd(&g_deg[d], 1);
                if (pos < CAP) g_pairs2[d * CAP + pos] = p;
            }
        } else {
            for (int e = base; e < E; e++) {
                int d = dst[e];
                unsigned short p = (unsigned short)((nid[src[e]] << 4) | typ[e]);
                int pos = atomicAdd(&g_deg[d], 1);
                if (pos < CAP) g_pairs2[d * CAP + pos] = p;
            }
        }
    }
}

// ---------------- fused gather + GRU + score: one warp per node ----------------
__device__ __forceinline__ float sigmoidf_(float x) { return 1.f / (1.f + __expf(-x)); }

__global__ void __launch_bounds__(256, 6) k_main(
    const int* __restrict__ nid, const float* __restrict__ emb,
    const float* __restrict__ b_ih, const float* __restrict__ score_w,
    const float* __restrict__ score_b, float* __restrict__ out, int N) {
    int d = (blockIdx.x * blockDim.x + threadIdx.x) >> 5;
    int lane = threadIdx.x & 31;
    if (d >= N) return;

    int deg = g_deg[d];
    int degc = min(deg, CAP);
    const unsigned short* pl = &g_pairs2[d * CAP];

    float a0 = 0.f, a1 = 0.f, a2 = 0.f, a3 = 0.f, a4 = 0.f, a5 = 0.f;

    int c = 0;
    // full 8-edge chunks, two independent fp16 accumulator sets (even/odd edge)
    for (; c + 8 <= degc; c += 8) {
        uint4 pk = __ldg((const uint4*)(pl + c));
        __half2 pa0 = __float2half2_rn(0.f), pa1 = pa0, pa2 = pa0;
        __half2 pb0 = pa0, pb1 = pa0, pb2 = pa0;
        unsigned w[4] = {pk.x, pk.y, pk.z, pk.w};
        #pragma unroll
        for (int q = 0; q < 4; q++) {
            unsigned p0 = w[q] & 0xFFFFu;
            unsigned p1 = w[q] >> 16;
            const __half2* r0 = &g_M2h[p0 * H2C + lane];
            const __half2* r1 = &g_M2h[p1 * H2C + lane];
            pa0 = __hadd2(pa0, __ldg(r0));
            pa1 = __hadd2(pa1, __ldg(r0 + 32));
            pa2 = __hadd2(pa2, __ldg(r0 + 64));
            pb0 = __hadd2(pb0, __ldg(r1));
            pb1 = __hadd2(pb1, __ldg(r1 + 32));
            pb2 = __hadd2(pb2, __ldg(r1 + 64));
        }
        float2 f0 = __half22float2(__hadd2(pa0, pb0));
        float2 f1 = __half22float2(__hadd2(pa1, pb1));
        float2 f2 = __half22float2(__hadd2(pa2, pb2));
        a0 += f0.x; a3 += f0.y;
        a1 += f1.x; a4 += f1.y;
        a2 += f2.x; a5 += f2.y;
    }
    // tail chunk: out-of-range slots -> zero null-row (pl+c read is in-bounds: c <= 88)
    if (c < degc) {
        uint4 pk = __ldg((const uint4*)(pl + c));
        __half2 pa0 = __float2half2_rn(0.f), pa1 = pa0, pa2 = pa0;
        __half2 pb0 = pa0, pb1 = pa0, pb2 = pa0;
        unsigned w[4] = {pk.x, pk.y, pk.z, pk.w};
        int m = degc - c;
        #pragma unroll
        for (int q = 0; q < 4; q++) {
            unsigned p0 = (2 * q     < m) ? (w[q] & 0xFFFFu) : (unsigned)NPAIR;
            unsigned p1 = (2 * q + 1 < m) ? (w[q] >> 16)     : (unsigned)NPAIR;
            const __half2* r0 = &g_M2h[p0 * H2C + lane];
            const __half2* r1 = &g_M2h[p1 * H2C + lane];
            pa0 = __hadd2(pa0, __ldg(r0));
            pa1 = __hadd2(pa1, __ldg(r0 + 32));
            pa2 = __hadd2(pa2, __ldg(r0 + 64));
            pb0 = __hadd2(pb0, __ldg(r1));
            pb1 = __hadd2(pb1, __ldg(r1 + 32));
            pb2 = __hadd2(pb2, __ldg(r1 + 64));
        }
        float2 f0 = __half22float2(__hadd2(pa0, pb0));
        float2 f1 = __half22float2(__hadd2(pa1, pb1));
        float2 f2 = __half22float2(__hadd2(pa2, pb2));
        a0 += f0.x; a3 += f0.y;
        a1 += f1.x; a4 += f1.y;
        a2 += f2.x; a5 += f2.y;
    }

    float inv = 1.f / fmaxf((float)deg, 1.f);
    int v = nid[d];
    const float* gh = &g_gh[v * G3];

    float r0 = sigmoidf_(a0 * inv + __ldg(&b_ih[lane])       + gh[lane]);
    float r1 = sigmoidf_(a1 * inv + __ldg(&b_ih[lane + 32])  + gh[lane + 32]);
    float z0 = sigmoidf_(a2 * inv + __ldg(&b_ih[lane + 64])  + gh[lane + 64]);
    float z1 = sigmoidf_(a3 * inv + __ldg(&b_ih[lane + 96])  + gh[lane + 96]);
    float n0 = tanhf(a4 * inv + __ldg(&b_ih[lane + 128]) + r0 * gh[lane + 128]);
    float n1 = tanhf(a5 * inv + __ldg(&b_ih[lane + 160]) + r1 * gh[lane + 160]);

    float h0 = __ldg(&emb[v * EMB + lane]);
    float h1 = __ldg(&emb[v * EMB + lane + 32]);
    float hn0 = (1.f - z0) * n0 + z0 * h0;
    float hn1 = (1.f - z1) * n1 + z1 * h1;

    float part = hn0 * __ldg(&score_w[lane]) + hn1 * __ldg(&score_w[lane + 32]);
    #pragma unroll
    for (int o = 16; o > 0; o >>= 1) part += __shfl_down_sync(0xffffffffu, part, o);
    if (lane == 0) out[d] = part + score_b[0];
}

// ---------------- launcher ----------------
extern "C" void kernel_launch(void* const* d_in, const int* in_sizes, int n_in,
                              void* d_out, int out_size) {
    const int*   node_ids  = (const int*)  d_in[0];
    const int*   edge_src  = (const int*)  d_in[1];
    const int*   edge_dst  = (const int*)  d_in[2];
    const int*   edge_type = (const int*)  d_in[3];
    const float* emb       = (const float*)d_in[4];
    const float* eemb      = (const float*)d_in[5];
    const float* W1        = (const float*)d_in[6];
    const float* b1        = (const float*)d_in[7];
    const float* W2        = (const float*)d_in[8];
    const float* b2        = (const float*)d_in[9];
    const float* W_ih      = (const float*)d_in[10];
    const float* W_hh      = (const float*)d_in[11];
    const float* b_ih      = (const float*)d_in[12];
    const float* b_hh      = (const float*)d_in[13];
    const float* score_w   = (const float*)d_in[14];
    const float* score_b   = (const float*)d_in[15];
    float* out = (float*)d_out;

    int N = in_sizes[0];
    int E = in_sizes[1];

    void* degp = nullptr;
    cudaGetSymbolAddress(&degp, g_deg);
    cudaMemsetAsync(degp, 0, (size_t)N * sizeof(int));

    int scat_blocks = (E + 767) / 768;
    k_work<<<NPAIR + 1 + VOCAB + scat_blocks, 192>>>(
        node_ids, edge_src, edge_dst, edge_type, E,
        emb, eemb, W1, b1, W2, b2, W_ih, W_hh, b_hh);

    k_main<<<(N * 32 + 255) / 256, 256>>>(node_ids, emb, b_ih, score_w, score_b, out, N);
}

// round 7
// speedup vs baseline: 1.1332x; 1.0527x over previous
#include <cuda_runtime.h>
#include <cuda_fp16.h>

#define NMAX   100000
#define VOCAB  32
#define NTYPE  16
#define EMB    64
#define MSGD   128
#define EEMB   32
#define CIN    (EMB + EEMB)      // 96
#define NPAIR  (VOCAB * NTYPE)   // 512
#define G3     192               // 3*EMB
#define ROWW   96                // 32-bit words per table row (384 B, no pad)
#define CAP    96                // per-node bucket capacity (multiple of 8)

// ---------------- static scratch ----------------
// Packed fp16 gather table, 384 B/row, 513 rows (+zero null-row):
//   words [0,64):  lane-major uint2 -> half2 (M2[L],M2[L+96]) , (M2[L+32],M2[L+128])
//   words [64,96): lane-major uint  -> half2 (M2[L+64],M2[L+160])
__device__ __align__(16) unsigned g_tabw[(NPAIR + 1) * ROWW];  // 192.4 KB, L1-resident
__device__ float g_ghb[VOCAB * G3];      // gh + b_ih (k<128), raw gh (k>=128)
__device__ int   g_deg[NMAX];            // zeroed via memsetAsync
__device__ __align__(16) unsigned short g_pairs2[NMAX * CAP];  // 19.2 MB buckets

// ---------------- fused front-end: tables + bucket scatter ----------------
__global__ void __launch_bounds__(192) k_work(
    const int* __restrict__ nid, const int* __restrict__ src,
    const int* __restrict__ dst, const int* __restrict__ typ, int E,
    const float* __restrict__ emb, const float* __restrict__ eemb,
    const float* __restrict__ W1, const float* __restrict__ b1,
    const float* __restrict__ W2, const float* __restrict__ b2,
    const float* __restrict__ W_ih, const float* __restrict__ b_ih,
    const float* __restrict__ W_hh, const float* __restrict__ b_hh) {
    int b = blockIdx.x, tid = threadIdx.x;
    if (b < NPAIR) {
        __shared__ float x[CIN];
        __shared__ float hid[MSGD];
        __shared__ float msg[MSGD];
        __shared__ float m2[G3];
        int v = b >> 4, t = b & 15;
        if (tid < EMB)       x[tid] = emb[v * EMB + tid];
        else if (tid < CIN)  x[tid] = eemb[t * EEMB + (tid - EMB)];
        __syncthreads();
        if (tid < MSGD) {
            float s = b1[tid];
            #pragma unroll 8
            for (int i = 0; i < CIN; i++) s += x[i] * W1[i * MSGD + tid];
            hid[tid] = fmaxf(s, 0.f);
        }
        __syncthreads();
        if (tid < MSGD) {
            float m = b2[tid];
            #pragma unroll 8
            for (int i = 0; i < MSGD; i++) m += hid[i] * W2[i * MSGD + tid];
            msg[tid] = m;
        }
        __syncthreads();
        {
            float s = 0.f;
            #pragma unroll 8
            for (int j = 0; j < MSGD; j++) s += msg[j] * W_ih[j * G3 + tid];
            m2[tid] = s;
        }
        __syncthreads();
        if (tid < 32) {
            int L = tid;
            __half2 A = __floats2half2_rn(m2[L],      m2[L + 96]);
            __half2 B = __floats2half2_rn(m2[L + 32], m2[L + 128]);
            __half2 C = __floats2half2_rn(m2[L + 64], m2[L + 160]);
            unsigned base = b * ROWW;
            g_tabw[base + L * 2]     = *reinterpret_cast<unsigned*>(&A);
            g_tabw[base + L * 2 + 1] = *reinterpret_cast<unsigned*>(&B);
            g_tabw[base + 64 + L]    = *reinterpret_cast<unsigned*>(&C);
        }
    } else if (b == NPAIR) {
        if (tid < ROWW) g_tabw[NPAIR * ROWW + tid] = 0u;       // null row
    } else if (b < NPAIR + 1 + VOCAB) {
        __shared__ float h[EMB];
        int v = b - NPAIR - 1;
        if (tid < EMB) h[tid] = emb[v * EMB + tid];
        __syncthreads();
        float s = b_hh[tid];
        #pragma unroll 8
        for (int j = 0; j < EMB; j++) s += h[j] * W_hh[j * G3 + tid];
        if (tid < 128) s += b_ih[tid];     // fold b_ih for r/z gates only
        g_ghb[v * G3 + tid] = s;
    } else {
        int base = (b - NPAIR - 1 - VOCAB) * 768 + tid * 4;
        if (base + 3 < E) {
            int4 s4 = *(const int4*)(src + base);
            int4 d4 = *(const int4*)(dst + base);
            int4 t4 = *(const int4*)(typ + base);
            #pragma unroll
            for (int k = 0; k < 4; k++) {
                int d = (&d4.x)[k];
                unsigned short p = (unsigned short)((nid[(&s4.x)[k]] << 4) | (&t4.x)[k]);
                int pos = atomicAdd(&g_deg[d], 1);
                if (pos < CAP) g_pairs2[d * CAP + pos] = p;
            }
        } else {
            for (int e = base; e < E; e++) {
                int d = dst[e];
                unsigned short p = (unsigned short)((nid[src[e]] << 4) | typ[e]);
                int pos = atomicAdd(&g_deg[d], 1);
                if (pos < CAP) g_pairs2[d * CAP + pos] = p;
            }
        }
    }
}

// ---------------- fast activations (MUFU.TANH) ----------------
__device__ __forceinline__ float tanh_fast(float x) {
    float y;
    asm("tanh.approx.f32 %0, %1;" : "=f"(y) : "f"(x));
    return y;
}
__device__ __forceinline__ float sig_fast(float x) {
    return fmaf(tanh_fast(0.5f * x), 0.5f, 0.5f);
}

// ---------------- fused gather + GRU + score: one warp per node ----------------
__global__ void __launch_bounds__(256, 6) k_main(
    const int* __restrict__ nid, const float* __restrict__ emb,
    const float* __restrict__ b_ih, const float* __restrict__ score_w,
    const float* __restrict__ score_b, float* __restrict__ out, int N) {
    int d = (blockIdx.x * blockDim.x + threadIdx.x) >> 5;
    int lane = threadIdx.x & 31;
    if (d >= N) return;

    int deg = g_deg[d];
    int degc = min(deg, CAP);
    const unsigned short* pl = &g_pairs2[d * CAP];

    float a0 = 0.f, a1 = 0.f, a2 = 0.f, a3 = 0.f, a4 = 0.f, a5 = 0.f;

    int c = 0;
    // full 8-edge chunks, two independent fp16 accumulator sets
    for (; c + 8 <= degc; c += 8) {
        uint4 pk = __ldg((const uint4*)(pl + c));
        __half2 pa0 = __float2half2_rn(0.f), pa1 = pa0, pa2 = pa0;
        __half2 pb0 = pa0, pb1 = pa0, pb2 = pa0;
        unsigned w[4] = {pk.x, pk.y, pk.z, pk.w};
        #pragma unroll
        for (int q = 0; q < 4; q++) {
            unsigned p0 = w[q] & 0xFFFFu;
            unsigned p1 = w[q] >> 16;
            const unsigned* r0 = g_tabw + p0 * ROWW;
            const unsigned* r1 = g_tabw + p1 * ROWW;
            uint2 ab0 = __ldg((const uint2*)r0 + lane);
            unsigned c0 = __ldg(r0 + 64 + lane);
            uint2 ab1 = __ldg((const uint2*)r1 + lane);
            unsigned c1 = __ldg(r1 + 64 + lane);
            pa0 = __hadd2(pa0, *reinterpret_cast<__half2*>(&ab0.x));
            pa1 = __hadd2(pa1, *reinterpret_cast<__half2*>(&ab0.y));
            pa2 = __hadd2(pa2, *reinterpret_cast<__half2*>(&c0));
            pb0 = __hadd2(pb0, *reinterpret_cast<__half2*>(&ab1.x));
            pb1 = __hadd2(pb1, *reinterpret_cast<__half2*>(&ab1.y));
            pb2 = __hadd2(pb2, *reinterpret_cast<__half2*>(&c1));
        }
        float2 f0 = __half22float2(__hadd2(pa0, pb0));
        float2 f1 = __half22float2(__hadd2(pa1, pb1));
        float2 f2 = __half22float2(__hadd2(pa2, pb2));
        a0 += f0.x; a3 += f0.y;
        a1 += f1.x; a4 += f1.y;
        a2 += f2.x; a5 += f2.y;
    }
    // tail chunk: out-of-range slots -> zero null-row (pl+c read in-bounds: c <= 88)
    if (c < degc) {
        uint4 pk = __ldg((const uint4*)(pl + c));
        __half2 pa0 = __float2half2_rn(0.f), pa1 = pa0, pa2 = pa0;
        __half2 pb0 = pa0, pb1 = pa0, pb2 = pa0;
        unsigned w[4] = {pk.x, pk.y, pk.z, pk.w};
        int m = degc - c;
        #pragma unroll
        for (int q = 0; q < 4; q++) {
            unsigned p0 = (2 * q     < m) ? (w[q] & 0xFFFFu) : (unsigned)NPAIR;
            unsigned p1 = (2 * q + 1 < m) ? (w[q] >> 16)     : (unsigned)NPAIR;
            const unsigned* r0 = g_tabw + p0 * ROWW;
            const unsigned* r1 = g_tabw + p1 * ROWW;
            uint2 ab0 = __ldg((const uint2*)r0 + lane);
            unsigned c0 = __ldg(r0 + 64 + lane);
            uint2 ab1 = __ldg((const uint2*)r1 + lane);
            unsigned c1 = __ldg(r1 + 64 + lane);
            pa0 = __hadd2(pa0, *reinterpret_cast<__half2*>(&ab0.x));
            pa1 = __hadd2(pa1, *reinterpret_cast<__half2*>(&ab0.y));
            pa2 = __hadd2(pa2, *reinterpret_cast<__half2*>(&c0));
            pb0 = __hadd2(pb0, *reinterpret_cast<__half2*>(&ab1.x));
            pb1 = __hadd2(pb1, *reinterpret_cast<__half2*>(&ab1.y));
            pb2 = __hadd2(pb2, *reinterpret_cast<__half2*>(&c1));
        }
        float2 f0 = __half22float2(__hadd2(pa0, pb0));
        float2 f1 = __half22float2(__hadd2(pa1, pb1));
        float2 f2 = __half22float2(__hadd2(pa2, pb2));
        a0 += f0.x; a3 += f0.y;
        a1 += f1.x; a4 += f1.y;
        a2 += f2.x; a5 += f2.y;
    }

    float inv = 1.f / fmaxf((float)deg, 1.f);
    int v = nid[d];
    const float* ghb = &g_ghb[v * G3];

    float r0 = sig_fast(a0 * inv + ghb[lane]);
    float r1 = sig_fast(a1 * inv + ghb[lane + 32]);
    float z0 = sig_fast(a2 * inv + ghb[lane + 64]);
    float z1 = sig_fast(a3 * inv + ghb[lane + 96]);
    float n0 = tanh_fast(a4 * inv + __ldg(&b_ih[lane + 128]) + r0 * ghb[lane + 128]);
    float n1 = tanh_fast(a5 * inv + __ldg(&b_ih[lane + 160]) + r1 * ghb[lane + 160]);

    float h0 = __ldg(&emb[v * EMB + lane]);
    float h1 = __ldg(&emb[v * EMB + lane + 32]);
    float hn0 = (1.f - z0) * n0 + z0 * h0;
    float hn1 = (1.f - z1) * n1 + z1 * h1;

    float part = hn0 * __ldg(&score_w[lane]) + hn1 * __ldg(&score_w[lane + 32]);
    #pragma unroll
    for (int o = 16; o > 0; o >>= 1) part += __shfl_down_sync(0xffffffffu, part, o);
    if (lane == 0) out[d] = part + score_b[0];
}

// ---------------- launcher ----------------
extern "C" void kernel_launch(void* const* d_in, const int* in_sizes, int n_in,
                              void* d_out, int out_size) {
    const int*   node_ids  = (const int*)  d_in[0];
    const int*   edge_src  = (const int*)  d_in[1];
    const int*   edge_dst  = (const int*)  d_in[2];
    const int*   edge_type = (const int*)  d_in[3];
    const float* emb       = (const float*)d_in[4];
    const float* eemb      = (const float*)d_in[5];
    const float* W1        = (const float*)d_in[6];
    const float* b1        = (const float*)d_in[7];
    const float* W2        = (const float*)d_in[8];
    const float* b2        = (const float*)d_in[9];
    const float* W_ih      = (const float*)d_in[10];
    const float* W_hh      = (const float*)d_in[11];
    const float* b_ih      = (const float*)d_in[12];
    const float* b_hh      = (const float*)d_in[13];
    const float* score_w   = (const float*)d_in[14];
    const float* score_b   = (const float*)d_in[15];
    float* out = (float*)d_out;

    int N = in_sizes[0];
    int E = in_sizes[1];

    void* degp = nullptr;
    cudaGetSymbolAddress(&degp, g_deg);
    cudaMemsetAsync(degp, 0, (size_t)N * sizeof(int));

    int scat_blocks = (E + 767) / 768;
    k_work<<<NPAIR + 1 + VOCAB + scat_blocks, 192>>>(
        node_ids, edge_src, edge_dst, edge_type, E,
        emb, eemb, W1, b1, W2, b2, W_ih, b_ih, W_hh, b_hh);

    k_main<<<(N * 32 + 255) / 256, 256>>>(node_ids, emb, b_ih, score_w, score_b, out, N);
}

// round 8
// speedup vs baseline: 1.2124x; 1.0699x over previous
#include <cuda_runtime.h>
#include <cuda_fp16.h>

#define NMAX   100000
#define VOCAB  32
#define NTYPE  16
#define EMB    64
#define MSGD   128
#define EEMB   32
#define CIN    (EMB + EEMB)      // 96
#define NPAIR  (VOCAB * NTYPE)   // 512
#define G3     192               // 3*EMB
#define ROWW   96                // 32-bit words per table row (384 B, no pad)
#define CAP    96                // per-node bucket capacity (multiple of 8)

// ---------------- static scratch ----------------
// Packed fp16 gather table, 384 B/row:
//   words [0,64):  lane-major uint2 -> half2 (M2[L],M2[L+96]) , (M2[L+32],M2[L+128])
//   words [64,96): lane-major uint  -> half2 (M2[L+64],M2[L+160])
__device__ __align__(16) unsigned g_tabw[NPAIR * ROWW];        // 192 KB, L1-resident
// Per-(vocab,lane) epilogue row: 8 halves = {ghr0,ghr1, ghz0,ghz1, ghn0,ghn1, h0,h1}
__device__ __align__(16) uint4 g_epi[VOCAB * 32];              // 16 KB
__device__ int g_deg[NMAX];                                    // zeroed via memsetAsync
__device__ __align__(16) unsigned short g_pairs2[NMAX * CAP];  // 19.2 MB buckets

// ---------------- fused front-end: tables + bucket scatter ----------------
__global__ void __launch_bounds__(192) k_work(
    const int* __restrict__ nid, const int* __restrict__ src,
    const int* __restrict__ dst, const int* __restrict__ typ, int E,
    const float* __restrict__ emb, const float* __restrict__ eemb,
    const float* __restrict__ W1, const float* __restrict__ b1,
    const float* __restrict__ W2, const float* __restrict__ b2,
    const float* __restrict__ W_ih, const float* __restrict__ b_ih,
    const float* __restrict__ W_hh, const float* __restrict__ b_hh) {
    int b = blockIdx.x, tid = threadIdx.x;
    if (b < NPAIR) {
        __shared__ float x[CIN];
        __shared__ float hid[MSGD];
        __shared__ float msg[MSGD];
        __shared__ float m2[G3];
        int v = b >> 4, t = b & 15;
        if (tid < EMB)       x[tid] = emb[v * EMB + tid];
        else if (tid < CIN)  x[tid] = eemb[t * EEMB + (tid - EMB)];
        __syncthreads();
        if (tid < MSGD) {
            float s = b1[tid];
            #pragma unroll 8
            for (int i = 0; i < CIN; i++) s += x[i] * W1[i * MSGD + tid];
            hid[tid] = fmaxf(s, 0.f);
        }
        __syncthreads();
        if (tid < MSGD) {
            float m = b2[tid];
            #pragma unroll 8
            for (int i = 0; i < MSGD; i++) m += hid[i] * W2[i * MSGD + tid];
            msg[tid] = m;
        }
        __syncthreads();
        {
            float s = 0.f;
            #pragma unroll 8
            for (int j = 0; j < MSGD; j++) s += msg[j] * W_ih[j * G3 + tid];
            m2[tid] = s;
        }
        __syncthreads();
        if (tid < 32) {
            int L = tid;
            __half2 A = __floats2half2_rn(m2[L],      m2[L + 96]);
            __half2 B = __floats2half2_rn(m2[L + 32], m2[L + 128]);
            __half2 C = __floats2half2_rn(m2[L + 64], m2[L + 160]);
            unsigned base = b * ROWW;
            g_tabw[base + L * 2]     = *reinterpret_cast<unsigned*>(&A);
            g_tabw[base + L * 2 + 1] = *reinterpret_cast<unsigned*>(&B);
            g_tabw[base + 64 + L]    = *reinterpret_cast<unsigned*>(&C);
        }
    } else if (b < NPAIR + VOCAB) {
        __shared__ float h[EMB];
        __shared__ float gh[G3];
        int v = b - NPAIR;
        if (tid < EMB) h[tid] = emb[v * EMB + tid];
        __syncthreads();
        float s = b_hh[tid];
        #pragma unroll 8
        for (int j = 0; j < EMB; j++) s += h[j] * W_hh[j * G3 + tid];
        gh[tid] = s;
        __syncthreads();
        if (tid < 32) {
            int L = tid;
            __half2 rr = __floats2half2_rn(gh[L]      + b_ih[L],
                                           gh[L + 32] + b_ih[L + 32]);
            __half2 zz = __floats2half2_rn(gh[L + 64] + b_ih[L + 64],
                                           gh[L + 96] + b_ih[L + 96]);
            __half2 nn = __floats2half2_rn(gh[L + 128], gh[L + 160]);
            __half2 hh = __floats2half2_rn(h[L], h[L + 32]);
            uint4 pk;
            pk.x = *reinterpret_cast<unsigned*>(&rr);
            pk.y = *reinterpret_cast<unsigned*>(&zz);
            pk.z = *reinterpret_cast<unsigned*>(&nn);
            pk.w = *reinterpret_cast<unsigned*>(&hh);
            g_epi[v * 32 + L] = pk;
        }
    } else {
        int base = (b - NPAIR - VOCAB) * 768 + tid * 4;
        if (base + 3 < E) {
            int4 s4 = *(const int4*)(src + base);
            int4 d4 = *(const int4*)(dst + base);
            int4 t4 = *(const int4*)(typ + base);
            #pragma unroll
            for (int k = 0; k < 4; k++) {
                int d = (&d4.x)[k];
                unsigned short p = (unsigned short)((nid[(&s4.x)[k]] << 4) | (&t4.x)[k]);
                int pos = atomicAdd(&g_deg[d], 1);
                if (pos < CAP) g_pairs2[d * CAP + pos] = p;
            }
        } else {
            for (int e = base; e < E; e++) {
                int d = dst[e];
                unsigned short p = (unsigned short)((nid[src[e]] << 4) | typ[e]);
                int pos = atomicAdd(&g_deg[d], 1);
                if (pos < CAP) g_pairs2[d * CAP + pos] = p;
            }
        }
    }
}

// ---------------- fast activations (MUFU.TANH) ----------------
__device__ __forceinline__ float tanh_fast(float x) {
    float y;
    asm("tanh.approx.f32 %0, %1;" : "=f"(y) : "f"(x));
    return y;
}
__device__ __forceinline__ float sig_fast(float x) {
    return fmaf(tanh_fast(0.5f * x), 0.5f, 0.5f);
}

// gather one table row into fp16 accumulators
__device__ __forceinline__ void gather1(unsigned p, int lane,
                                        __half2& q0, __half2& q1, __half2& q2) {
    const unsigned* r = g_tabw + p * ROWW;
    uint2 ab = __ldg((const uint2*)r + lane);
    unsigned cc = __ldg(r + 64 + lane);
    q0 = __hadd2(q0, *reinterpret_cast<__half2*>(&ab.x));
    q1 = __hadd2(q1, *reinterpret_cast<__half2*>(&ab.y));
    q2 = __hadd2(q2, *reinterpret_cast<__half2*>(&cc));
}

// ---------------- persistent fused gather + GRU + score: one warp per node ----------------
__global__ void __launch_bounds__(256, 6) k_main(
    const int* __restrict__ nid, const float* __restrict__ b_ih,
    const float* __restrict__ score_w, const float* __restrict__ score_b,
    float* __restrict__ out, int N) {
    int lane = threadIdx.x & 31;
    int gw = (blockIdx.x * blockDim.x + threadIdx.x) >> 5;
    int stride = (gridDim.x * blockDim.x) >> 5;

    // per-warp loop-invariant constants
    float sw0 = __ldg(&score_w[lane]);
    float sw1 = __ldg(&score_w[lane + 32]);
    float bn0 = __ldg(&b_ih[lane + 128]);
    float bn1 = __ldg(&b_ih[lane + 160]);
    float sb  = __ldg(score_b);

    for (int d = gw; d < N; d += stride) {
        int deg = __ldg(&g_deg[d]);
        int degc = min(deg, CAP);
        const unsigned short* pl = &g_pairs2[d * CAP];

        float a0 = 0.f, a1 = 0.f, a2 = 0.f, a3 = 0.f, a4 = 0.f, a5 = 0.f;

        int c = 0;
        // full 8-edge chunks, two independent fp16 accumulator sets
        for (; c + 8 <= degc; c += 8) {
            uint4 pk = __ldg((const uint4*)(pl + c));
            __half2 pa0 = __float2half2_rn(0.f), pa1 = pa0, pa2 = pa0;
            __half2 pb0 = pa0, pb1 = pa0, pb2 = pa0;
            unsigned w[4] = {pk.x, pk.y, pk.z, pk.w};
            #pragma unroll
            for (int q = 0; q < 4; q++) {
                gather1(w[q] & 0xFFFFu, lane, pa0, pa1, pa2);
                gather1(w[q] >> 16,     lane, pb0, pb1, pb2);
            }
            float2 f0 = __half22float2(__hadd2(pa0, pb0));
            float2 f1 = __half22float2(__hadd2(pa1, pb1));
            float2 f2 = __half22float2(__hadd2(pa2, pb2));
            a0 += f0.x; a3 += f0.y;
            a1 += f1.x; a4 += f1.y;
            a2 += f2.x; a5 += f2.y;
        }
        // exact tail: one in-bounds uint4 pair read (CAP multiple of 8), m in [1,7]
        int m = degc - c;
        if (m > 0) {
            uint4 pk = __ldg((const uint4*)(pl + c));
            __half2 pa0 = __float2half2_rn(0.f), pa1 = pa0, pa2 = pa0;
            unsigned w[4] = {pk.x, pk.y, pk.z, pk.w};
            #pragma unroll
            for (int j = 0; j < 7; j++) {
                if (j >= m) break;
                unsigned word = w[j >> 1];
                unsigned p = (j & 1) ? (word >> 16) : (word & 0xFFFFu);
                gather1(p, lane, pa0, pa1, pa2);
            }
            float2 f0 = __half22float2(pa0);
            float2 f1 = __half22float2(pa1);
            float2 f2 = __half22float2(pa2);
            a0 += f0.x; a3 += f0.y;
            a1 += f1.x; a4 += f1.y;
            a2 += f2.x; a5 += f2.y;
        }

        float inv = __fdividef(1.f, fmaxf((float)deg, 1.f));
        int v = __ldg(&nid[d]);
        uint4 ep = __ldg(&g_epi[v * 32 + lane]);
        float2 grr = __half22float2(*reinterpret_cast<__half2*>(&ep.x));
        float2 gzz = __half22float2(*reinterpret_cast<__half2*>(&ep.y));
        float2 gnn = __half22float2(*reinterpret_cast<__half2*>(&ep.z));
        float2 ghh = __half22float2(*reinterpret_cast<__half2*>(&ep.w));

        float r0 = sig_fast(a0 * inv + grr.x);
        float r1 = sig_fast(a1 * inv + grr.y);
        float z0 = sig_fast(a2 * inv + gzz.x);
        float z1 = sig_fast(a3 * inv + gzz.y);
        float n0 = tanh_fast(a4 * inv + bn0 + r0 * gnn.x);
        float n1 = tanh_fast(a5 * inv + bn1 + r1 * gnn.y);

        float hn0 = (1.f - z0) * n0 + z0 * ghh.x;
        float hn1 = (1.f - z1) * n1 + z1 * ghh.y;

        float part = hn0 * sw0 + hn1 * sw1;
        #pragma unroll
        for (int o = 16; o > 0; o >>= 1) part += __shfl_down_sync(0xffffffffu, part, o);
        if (lane == 0) out[d] = part + sb;
    }
}

// ---------------- launcher ----------------
extern "C" void kernel_launch(void* const* d_in, const int* in_sizes, int n_in,
                              void* d_out, int out_size) {
    const int*   node_ids  = (const int*)  d_in[0];
    const int*   edge_src  = (const int*)  d_in[1];
    const int*   edge_dst  = (const int*)  d_in[2];
    const int*   edge_type = (const int*)  d_in[3];
    const float* emb       = (const float*)d_in[4];
    const float* eemb      = (const float*)d_in[5];
    const float* W1        = (const float*)d_in[6];
    const float* b1        = (const float*)d_in[7];
    const float* W2        = (const float*)d_in[8];
    const float* b2        = (const float*)d_in[9];
    const float* W_ih      = (const float*)d_in[10];
    const float* W_hh      = (const float*)d_in[11];
    const float* b_ih      = (const float*)d_in[12];
    const float* b_hh      = (const float*)d_in[13];
    const float* score_w   = (const float*)d_in[14];
    const float* score_b   = (const float*)d_in[15];
    float* out = (float*)d_out;

    int N = in_sizes[0];
    int E = in_sizes[1];

    void* degp = nullptr;
    cudaGetSymbolAddress(&degp, g_deg);
    cudaMemsetAsync(degp, 0, (size_t)N * sizeof(int));

    int scat_blocks = (E + 767) / 768;
    k_work<<<NPAIR + VOCAB + scat_blocks, 192>>>(
        node_ids, edge_src, edge_dst, edge_type, E,
        emb, eemb, W1, b1, W2, b2, W_ih, b_ih, W_hh, b_hh);

    // persistent: 6 blocks/SM x 148 SMs
    k_main<<<888, 256>>>(node_ids, b_ih, score_w, score_b, out, N);
}